// round 12
// baseline (speedup 1.0000x reference)
#include <cuda_runtime.h>
#include <math.h>

// B=4096 samples, M=4 modes, L=4 layers, D=8 cutoff.
// Padded SMEM state layout (float2 units): strides S0=648, S1=81, S2=9, S3=1.
// Size = 8*648 = 5184 float2 per buffer.

#define SZP 5184

__device__ float2 g_bs[48 * 512];          // 48 BS gates, packed [row][k] (8 per row, 0-padded)
__device__ float2 g_sq[16 * 64];           // [L][M] squeeze' (intf2 rot folded)
__device__ float2 g_dp[16 * 64];           // [L][M] disp' (Kerr + next intf1 rot folded)
__device__ float2 g_enc[4096 * 4 * 8];     // [B][M][8] encoding col-0 (rot1 l=0 folded)

__device__ __forceinline__ float2 cmul(float2 a, float2 b) {
    return make_float2(a.x * b.x - a.y * b.y, a.x * b.y + a.y * b.x);
}

// ---------------------------------------------------------------------------
// Block-cooperative expm: scaling-and-squaring + Taylor-12 (scaled norm <= 1).
// ---------------------------------------------------------------------------
__device__ float2* block_expm(float2* H, float2* P, float2* E, float2* T,
                              float* red, int* s_sh, int n, int ln) {
    const int tid = threadIdx.x, nt = blockDim.x, N2 = n * n;
    if (tid < n) {
        float s = 0.f;
        for (int c = 0; c < n; c++) { float2 h = H[(tid << ln) + c]; s += fabsf(h.x) + fabsf(h.y); }
        red[tid] = s;
    }
    __syncthreads();
    if (tid == 0) {
        float m = 0.f;
        for (int r = 0; r < n; r++) m = fmaxf(m, red[r]);
        int s = 0;
        while (m > 1.0f && s < 48) { m *= 0.5f; s++; }
        *s_sh = s;
    }
    __syncthreads();
    const int s = *s_sh;
    const float scale = ldexpf(1.0f, -s);
    for (int e = tid; e < N2; e += nt) { float2 h = H[e]; h.x *= scale; h.y *= scale; H[e] = h; }
    __syncthreads();
    for (int e = tid; e < N2; e += nt) {
        float2 h = H[e];
        P[e] = h;
        if ((e >> ln) == (e & (n - 1))) h.x += 1.0f;
        E[e] = h;
    }
    __syncthreads();
    for (int k = 2; k <= 12; k++) {
        const float inv = 1.0f / (float)k;
        for (int e = tid; e < N2; e += nt) {
            int r = e >> ln, c = e & (n - 1);
            float2 acc = make_float2(0.f, 0.f);
            for (int m = 0; m < n; m++) {
                float2 a = P[(r << ln) + m], b = H[(m << ln) + c];
                acc.x += a.x * b.x - a.y * b.y;
                acc.y += a.x * b.y + a.y * b.x;
            }
            acc.x *= inv; acc.y *= inv;
            T[e] = acc;
        }
        __syncthreads();
        for (int e = tid; e < N2; e += nt) { E[e].x += T[e].x; E[e].y += T[e].y; }
        { float2* tmp = P; P = T; T = tmp; }
        __syncthreads();
    }
    for (int q = 0; q < s; q++) {
        for (int e = tid; e < N2; e += nt) {
            int r = e >> ln, c = e & (n - 1);
            float2 acc = make_float2(0.f, 0.f);
            for (int m = 0; m < n; m++) {
                float2 a = E[(r << ln) + m], b = E[(m << ln) + c];
                acc.x += a.x * b.x - a.y * b.y;
                acc.y += a.x * b.y + a.y * b.x;
            }
            T[e] = acc;
        }
        __syncthreads();
        { float2* tmp = E; E = T; T = tmp; }
        __syncthreads();
    }
    return E;
}

// ---------------------------------------------------------------------------
// Shared gate precompute: 48 BS (64x64 -> packed 64x8) + 16 squeeze + 16 disp.
// ---------------------------------------------------------------------------
extern __shared__ float2 dynbuf[];

__global__ void __launch_bounds__(512) precomp_gates(
        const float* __restrict__ th1, const float* __restrict__ ph1,
        const float* __restrict__ th2, const float* __restrict__ ph2,
        const float* __restrict__ dr,  const float* __restrict__ dphi,
        const float* __restrict__ sr,  const float* __restrict__ sphi,
        const float* __restrict__ kp) {
    float2* H = dynbuf;
    float2* P = dynbuf + 4096;
    float2* E = dynbuf + 8192;
    float2* T = dynbuf + 12288;
    float*  red = (float*)(dynbuf + 16384);
    __shared__ int s_sh;
    const int bid = blockIdx.x, tid = threadIdx.x;
    const int nt = blockDim.x;

    if (bid < 48) {
        const int l = bid / 12, t = (bid / 6) % 2, p = bid % 6;
        const int PI6[6] = {0, 0, 0, 1, 1, 2}, PJ6[6] = {1, 2, 3, 2, 3, 3};
        const int i = PI6[p], j = PJ6[p];
        const float* TH = t ? th2 : th1;
        const float* PH = t ? ph2 : ph1;
        const float theta = TH[l * 16 + i * 4 + j];
        const float phi   = PH[l * 16 + i * 4 + j];
        const float post  = PH[l * 16 + j * 4 + i];   // rotation on mode j after BS
        float sp, cp;
        sincosf(phi, &sp, &cp);
        for (int e = tid; e < 4096; e += nt) {
            int R = e >> 6, C = e & 63;
            int a = R >> 3, b = R & 7, c = C >> 3, d = C & 7;
            float2 h = make_float2(0.f, 0.f);
            if (a == c - 1 && d == b - 1) {
                float co = theta * sqrtf((float)(c * b));
                h.x += co * cp; h.y += co * sp;
            }
            if (c == a - 1 && b == d - 1) {
                float co = theta * sqrtf((float)(a * d));
                h.x -= co * cp; h.y += co * sp;
            }
            H[e] = h;
        }
        __syncthreads();
        float2* R2 = block_expm(H, P, E, T, red, &s_sh, 64, 6);
        // pack: U block-diagonal in s=a+b. row (a,b): cols (c, s-c),
        // c in [max(0,s-7), min(7,s)], padded to 8 entries with zeros.
        // post-rotation phase e^{i post*b} folded into each row.
        for (int e = tid; e < 512; e += nt) {
            int row = e >> 3, k = e & 7;
            int a = row >> 3, b = row & 7, s = a + b;
            int cmin = s > 7 ? s - 7 : 0;
            int cmax = s < 7 ? s : 7;
            int c = cmin + k;
            float2 val = make_float2(0.f, 0.f);
            if (c <= cmax) {
                float2 v = R2[row * 64 + c * 8 + (s - c)];
                float si, co;
                sincosf(post * (float)b, &si, &co);
                val = make_float2(v.x * co - v.y * si, v.x * si + v.y * co);
            }
            g_bs[bid * 512 + e] = val;
        }
    } else {
        int g = bid - 48;
        const bool isSQ = (g < 16);
        if (!isSQ) g -= 16;
        const int l = g >> 2, w = g & 3;
        if (tid < 64) {
            int i = tid >> 3, k = tid & 7;
            float2 h = make_float2(0.f, 0.f);
            if (isSQ) {
                float r = sr[l * 4 + w], ph = sphi[l * 4 + w];
                float zr = r * cosf(ph), zi = r * sinf(ph);
                if (k == i + 2) {
                    float co = 0.5f * sqrtf((float)((i + 1) * (i + 2)));
                    h.x += co * zr; h.y -= co * zi;
                }
                if (i == k + 2) {
                    float co = 0.5f * sqrtf((float)((k + 1) * (k + 2)));
                    h.x -= co * zr; h.y -= co * zi;
                }
            } else {
                float r = dr[l * 4 + w], ph = dphi[l * 4 + w];
                float amp = r * cosf(ph), ang = r * sinf(ph);
                float ar = amp * cosf(ang), ai = amp * sinf(ang);
                if (k == i - 1) { float co = sqrtf((float)i); h.x += co * ar; h.y += co * ai; }
                if (i == k - 1) { float co = sqrtf((float)k); h.x -= co * ar; h.y += co * ai; }
            }
            H[tid] = h;
        }
        __syncthreads();
        float2* R2 = block_expm(H, P, E, T, red, &s_sh, 8, 3);
        if (tid < 64) {
            int i = tid >> 3;
            float ang;
            if (isSQ) {
                ang = ph2[l * 16 + w * 4 + w] * (float)i;          // intf2 pre-rot
            } else {
                ang = kp[l * 4 + w] * (float)(i * i);              // Kerr
                if (l < 3) ang += ph1[(l + 1) * 16 + w * 4 + w] * (float)i;
            }
            float si, co;
            sincosf(ang, &si, &co);
            float2 v = R2[tid];
            (isSQ ? g_sq : g_dp)[g * 64 + tid] =
                make_float2(v.x * co - v.y * si, v.x * si + v.y * co);
        }
    }
}

// ---------------------------------------------------------------------------
// Per-sample encoding: col 0 of expm(x(Ad - A)), layer-0 rot1 folded in.
// ---------------------------------------------------------------------------
__global__ void __launch_bounds__(64) precomp_enc(const float* __restrict__ x,
                                                  const float* __restrict__ ph1) {
    __shared__ float2 H[64], P[64], E[64], T[64];
    __shared__ float red[8];
    __shared__ int s_sh;
    const int bm = blockIdx.x, m = bm & 3, tid = threadIdx.x;
    const float xv = x[bm];
    if (tid < 64) {
        int i = tid >> 3, k = tid & 7;
        float h = 0.f;
        if (k == i - 1) h += xv * sqrtf((float)i);
        if (i == k - 1) h -= xv * sqrtf((float)k);
        H[tid] = make_float2(h, 0.f);
    }
    __syncthreads();
    float2* R = block_expm(H, P, E, T, red, &s_sh, 8, 3);
    if (tid < 8) {
        float ang = ph1[m * 4 + m] * (float)tid;
        float si, co;
        sincosf(ang, &si, &co);
        float2 v = R[tid * 8];
        g_enc[bm * 8 + tid] = make_float2(v.x * co - v.y * si, v.x * si + v.y * co);
    }
}

// ---------------------------------------------------------------------------
// Block-sparse BS apply, row-per-lane mapping.
// Thread = (row = tid&63, spectator-group sg = tid>>6 handling 16 spectators).
// Gate row cached in regs; 8 clamped input addresses precomputed per row;
// spectator offsets are compile-time immediates -> inner body = LDS + 4 FFMA.
// ---------------------------------------------------------------------------
template<int A1, int A2, int SPA, int SPB>
__device__ __forceinline__ void applyBS(const float2* __restrict__ gate,
                                        const float2* __restrict__ in,
                                        float2* __restrict__ out, int tid) {
    const int row = tid & 63;
    const int sg  = tid >> 6;
    const int a = row >> 3, b = row & 7, s = a + b;
    const int cmin = s > 7 ? s - 7 : 0;
    const int cnt  = (s > 7 ? 14 - s : s) + 1;
    float2 g[8];
#pragma unroll
    for (int k = 0; k < 8; k++) g[k] = gate[(row << 3) + k];
    const int sgo = sg * 2 * SPA;
    const int base = cmin * A1 + (s - cmin) * A2 + sgo;
    int addr[8];
#pragma unroll
    for (int k = 0; k < 8; k++) {
        int kc = k < cnt ? k : cnt - 1;     // clamp: padded k reads stay in-bounds (gate=0)
        addr[k] = base + kc * (A1 - A2);
    }
    const int ob = a * A1 + b * A2 + sgo;
#pragma unroll
    for (int i = 0; i < 16; i++) {
        const int off = (i >> 3) * SPA + (i & 7) * SPB;   // compile-time immediate
        float2 acc = make_float2(0.f, 0.f);
#pragma unroll
        for (int k = 0; k < 8; k++) {
            float2 sv = in[addr[k] + off];
            acc.x = fmaf(g[k].x, sv.x, fmaf(-g[k].y, sv.y, acc.x));
            acc.y = fmaf(g[k].x, sv.y, fmaf(g[k].y, sv.x, acc.y));
        }
        out[ob + off] = acc;
    }
}

// Single-mode 8x8 gate on mode with stride SW; spectator strides SL>SM>SS.
template<int SW, int SL, int SM, int SS>
__device__ __forceinline__ void applySingle(const float2* __restrict__ mg,
                                            float2* __restrict__ st, int tid) {
#pragma unroll
    for (int qq = 0; qq < 2; qq++) {
        int f = tid + qq * 256;
        int base = (f >> 6) * SL + ((f >> 3) & 7) * SM + (f & 7) * SS;
        float2 v[8];
#pragma unroll
        for (int k = 0; k < 8; k++) v[k] = st[base + k * SW];
#pragma unroll
        for (int i = 0; i < 8; i++) {
            float2 a = make_float2(0.f, 0.f);
#pragma unroll
            for (int k = 0; k < 8; k++) {
                float2 u = mg[i * 8 + k];
                a.x = fmaf(u.x, v[k].x, fmaf(-u.y, v[k].y, a.x));
                a.y = fmaf(u.x, v[k].y, fmaf(u.y, v[k].x, a.y));
            }
            st[base + i * SW] = a;   // inputs cached in v: in-place safe
        }
    }
}

__global__ void __launch_bounds__(256, 2) sim_kernel(float* __restrict__ out) {
    float2* sA = dynbuf;
    float2* sB = dynbuf + SZP;
    float2* gbuf = dynbuf + 2 * SZP;       // 512 float2
    __shared__ float2 enc[4][8];
    const int tid = threadIdx.x, b = blockIdx.x;

    if (tid < 32) enc[tid >> 3][tid & 7] = g_enc[b * 32 + tid];
    __syncthreads();
#pragma unroll
    for (int q = 0; q < 16; q++) {
        int idx = tid + q * 256;
        int i0 = idx >> 9, i1 = (idx >> 6) & 7, i2 = (idx >> 3) & 7, i3 = idx & 7;
        sA[i0 * 648 + i1 * 81 + i2 * 9 + i3] =
            cmul(cmul(enc[0][i0], enc[1][i1]), cmul(enc[2][i2], enc[3][i3]));
    }
    float2 *cur = sA, *nxt = sB;

    for (int l = 0; l < 4; l++) {
        for (int t = 0; t < 2; t++) {
            for (int p = 0; p < 6; p++) {
                __syncthreads();
                ((float4*)gbuf)[tid] = ((const float4*)(g_bs + (l * 12 + t * 6 + p) * 512))[tid];
                __syncthreads();
                switch (p) {
                    case 0: applyBS<648, 81,   9,  1>(gbuf, cur, nxt, tid); break;
                    case 1: applyBS<648,  9,  81,  1>(gbuf, cur, nxt, tid); break;
                    case 2: applyBS<648,  1,  81,  9>(gbuf, cur, nxt, tid); break;
                    case 3: applyBS< 81,  9, 648,  1>(gbuf, cur, nxt, tid); break;
                    case 4: applyBS< 81,  1, 648,  9>(gbuf, cur, nxt, tid); break;
                    case 5: applyBS<  9,  1, 648, 81>(gbuf, cur, nxt, tid); break;
                }
                { float2* tmp = cur; cur = nxt; nxt = tmp; }
            }
            const float2* gptr = (t == 0) ? g_sq : g_dp;
            for (int w = 0; w < 4; w++) {
                __syncthreads();
                if (tid < 64) gbuf[tid] = gptr[(l * 4 + w) * 64 + tid];
                __syncthreads();
                switch (w) {
                    case 0: applySingle<648,  81,  9, 1>(gbuf, cur, tid); break;
                    case 1: applySingle< 81, 648,  9, 1>(gbuf, cur, tid); break;
                    case 2: applySingle<  9, 648, 81, 1>(gbuf, cur, tid); break;
                    case 3: applySingle<  1, 648, 81, 9>(gbuf, cur, tid); break;
                }
            }
        }
    }
    __syncthreads();

    float acc[4] = {0.f, 0.f, 0.f, 0.f};
#pragma unroll
    for (int q = 0; q < 16; q++) {
        int idx = tid + q * 256;
        int i0 = idx >> 9, i1 = (idx >> 6) & 7, i2 = (idx >> 3) & 7, i3 = idx & 7;
        float2 v = cur[i0 * 648 + i1 * 81 + i2 * 9 + i3];
        float pr = v.x * v.x + v.y * v.y;
        acc[0] += (float)i0 * pr;
        acc[1] += (float)i1 * pr;
        acc[2] += (float)i2 * pr;
        acc[3] += (float)i3 * pr;
    }
    float* red = (float*)nxt;
#pragma unroll
    for (int w = 0; w < 4; w++) red[w * 256 + tid] = acc[w];
    __syncthreads();
    for (int s = 128; s > 0; s >>= 1) {
        if (tid < s) {
#pragma unroll
            for (int w = 0; w < 4; w++) red[w * 256 + tid] += red[w * 256 + tid + s];
        }
        __syncthreads();
    }
    if (tid < 4) out[b * 4 + tid] = red[tid * 256];
}

// ---------------------------------------------------------------------------
extern "C" void kernel_launch(void* const* d_in, const int* in_sizes, int n_in,
                              void* d_out, int out_size) {
    const float* x    = (const float*)d_in[0];
    const float* th1  = (const float*)d_in[1];
    const float* ph1  = (const float*)d_in[2];
    const float* th2  = (const float*)d_in[3];
    const float* ph2  = (const float*)d_in[4];
    const float* dr   = (const float*)d_in[5];
    const float* dphi = (const float*)d_in[6];
    const float* sr   = (const float*)d_in[7];
    const float* sphi = (const float*)d_in[8];
    const float* kp   = (const float*)d_in[9];
    float* out = (float*)d_out;

    const size_t smemG = 16384 * sizeof(float2) + 64 * sizeof(float);     // 131328
    const size_t smemS = (size_t)(2 * SZP + 512) * sizeof(float2);        //  87040
    cudaFuncSetAttribute(precomp_gates, cudaFuncAttributeMaxDynamicSharedMemorySize, (int)smemG);
    cudaFuncSetAttribute(sim_kernel,    cudaFuncAttributeMaxDynamicSharedMemorySize, (int)smemS);

    precomp_gates<<<80, 512, smemG>>>(th1, ph1, th2, ph2, dr, dphi, sr, sphi, kp);
    precomp_enc<<<16384, 64>>>(x, ph1);
    sim_kernel<<<4096, 256, smemS>>>(out);
}

// round 15
// speedup vs baseline: 1.1448x; 1.1448x over previous
#include <cuda_runtime.h>
#include <math.h>

// B=4096 samples, M=4 modes, L=4 layers, D=8 cutoff.
// Padded SMEM state layout (float2 units): strides S0=648, S1=81, S2=9, S3=1.
// Size = 8*648 = 5184 float2 per buffer.

#define SZP 5184

__device__ float2 g_bs[48 * 512];          // 48 BS gates, packed [k][row] (transposed, 0-padded)
__device__ float2 g_sq[16 * 64];           // [L][M] squeeze' (intf2 rot folded)
__device__ float2 g_dp[16 * 64];           // [L][M] disp' (Kerr + next intf1 rot folded)
__device__ float2 g_enc[4096 * 4 * 8];     // [B][M][8] encoding col-0 (rot1 l=0 folded)

__device__ __forceinline__ float2 cmul(float2 a, float2 b) {
    return make_float2(a.x * b.x - a.y * b.y, a.x * b.y + a.y * b.x);
}

// ---------------------------------------------------------------------------
// Block-cooperative expm: scaling-and-squaring + Taylor-12 (scaled norm <= 1).
// ---------------------------------------------------------------------------
__device__ float2* block_expm(float2* H, float2* P, float2* E, float2* T,
                              float* red, int* s_sh, int n, int ln) {
    const int tid = threadIdx.x, nt = blockDim.x, N2 = n * n;
    if (tid < n) {
        float s = 0.f;
        for (int c = 0; c < n; c++) { float2 h = H[(tid << ln) + c]; s += fabsf(h.x) + fabsf(h.y); }
        red[tid] = s;
    }
    __syncthreads();
    if (tid == 0) {
        float m = 0.f;
        for (int r = 0; r < n; r++) m = fmaxf(m, red[r]);
        int s = 0;
        while (m > 1.0f && s < 48) { m *= 0.5f; s++; }
        *s_sh = s;
    }
    __syncthreads();
    const int s = *s_sh;
    const float scale = ldexpf(1.0f, -s);
    for (int e = tid; e < N2; e += nt) { float2 h = H[e]; h.x *= scale; h.y *= scale; H[e] = h; }
    __syncthreads();
    for (int e = tid; e < N2; e += nt) {
        float2 h = H[e];
        P[e] = h;
        if ((e >> ln) == (e & (n - 1))) h.x += 1.0f;
        E[e] = h;
    }
    __syncthreads();
    for (int k = 2; k <= 12; k++) {
        const float inv = 1.0f / (float)k;
        for (int e = tid; e < N2; e += nt) {
            int r = e >> ln, c = e & (n - 1);
            float2 acc = make_float2(0.f, 0.f);
            for (int m = 0; m < n; m++) {
                float2 a = P[(r << ln) + m], b = H[(m << ln) + c];
                acc.x += a.x * b.x - a.y * b.y;
                acc.y += a.x * b.y + a.y * b.x;
            }
            acc.x *= inv; acc.y *= inv;
            T[e] = acc;
        }
        __syncthreads();
        for (int e = tid; e < N2; e += nt) { E[e].x += T[e].x; E[e].y += T[e].y; }
        { float2* tmp = P; P = T; T = tmp; }
        __syncthreads();
    }
    for (int q = 0; q < s; q++) {
        for (int e = tid; e < N2; e += nt) {
            int r = e >> ln, c = e & (n - 1);
            float2 acc = make_float2(0.f, 0.f);
            for (int m = 0; m < n; m++) {
                float2 a = E[(r << ln) + m], b = E[(m << ln) + c];
                acc.x += a.x * b.x - a.y * b.y;
                acc.y += a.x * b.y + a.y * b.x;
            }
            T[e] = acc;
        }
        __syncthreads();
        { float2* tmp = E; E = T; T = tmp; }
        __syncthreads();
    }
    return E;
}

// ---------------------------------------------------------------------------
// Shared gate precompute: 48 BS (64x64 -> packed [k][row]) + 16 sq + 16 disp.
// ---------------------------------------------------------------------------
extern __shared__ float2 dynbuf[];

__global__ void __launch_bounds__(512) precomp_gates(
        const float* __restrict__ th1, const float* __restrict__ ph1,
        const float* __restrict__ th2, const float* __restrict__ ph2,
        const float* __restrict__ dr,  const float* __restrict__ dphi,
        const float* __restrict__ sr,  const float* __restrict__ sphi,
        const float* __restrict__ kp) {
    float2* H = dynbuf;
    float2* P = dynbuf + 4096;
    float2* E = dynbuf + 8192;
    float2* T = dynbuf + 12288;
    float*  red = (float*)(dynbuf + 16384);
    __shared__ int s_sh;
    const int bid = blockIdx.x, tid = threadIdx.x;
    const int nt = blockDim.x;

    if (bid < 48) {
        const int l = bid / 12, t = (bid / 6) % 2, p = bid % 6;
        const int PI6[6] = {0, 0, 0, 1, 1, 2}, PJ6[6] = {1, 2, 3, 2, 3, 3};
        const int i = PI6[p], j = PJ6[p];
        const float* TH = t ? th2 : th1;
        const float* PH = t ? ph2 : ph1;
        const float theta = TH[l * 16 + i * 4 + j];
        const float phi   = PH[l * 16 + i * 4 + j];
        const float post  = PH[l * 16 + j * 4 + i];   // rotation on mode j after BS
        float sp, cp;
        sincosf(phi, &sp, &cp);
        for (int e = tid; e < 4096; e += nt) {
            int R = e >> 6, C = e & 63;
            int a = R >> 3, b = R & 7, c = C >> 3, d = C & 7;
            float2 h = make_float2(0.f, 0.f);
            if (a == c - 1 && d == b - 1) {
                float co = theta * sqrtf((float)(c * b));
                h.x += co * cp; h.y += co * sp;
            }
            if (c == a - 1 && b == d - 1) {
                float co = theta * sqrtf((float)(a * d));
                h.x -= co * cp; h.y += co * sp;
            }
            H[e] = h;
        }
        __syncthreads();
        float2* R2 = block_expm(H, P, E, T, red, &s_sh, 64, 6);
        // pack: U block-diagonal in s=a+b. row (a,b): cols (c, s-c),
        // c in [max(0,s-7), min(7,s)], k-padded to 8 with zeros.
        // Layout TRANSPOSED: g_bs[bid*512 + k*64 + row] (conflict-free lane loads).
        // post-rotation phase e^{i post*b} folded into each row.
        for (int e = tid; e < 512; e += nt) {
            int k = e >> 6, row = e & 63;
            int a = row >> 3, b = row & 7, s = a + b;
            int cmin = s > 7 ? s - 7 : 0;
            int cmax = s < 7 ? s : 7;
            int c = cmin + k;
            float2 val = make_float2(0.f, 0.f);
            if (c <= cmax) {
                float2 v = R2[row * 64 + c * 8 + (s - c)];
                float si, co;
                sincosf(post * (float)b, &si, &co);
                val = make_float2(v.x * co - v.y * si, v.x * si + v.y * co);
            }
            g_bs[bid * 512 + e] = val;
        }
    } else {
        int g = bid - 48;
        const bool isSQ = (g < 16);
        if (!isSQ) g -= 16;
        const int l = g >> 2, w = g & 3;
        if (tid < 64) {
            int i = tid >> 3, k = tid & 7;
            float2 h = make_float2(0.f, 0.f);
            if (isSQ) {
                float r = sr[l * 4 + w], ph = sphi[l * 4 + w];
                float zr = r * cosf(ph), zi = r * sinf(ph);
                if (k == i + 2) {
                    float co = 0.5f * sqrtf((float)((i + 1) * (i + 2)));
                    h.x += co * zr; h.y -= co * zi;
                }
                if (i == k + 2) {
                    float co = 0.5f * sqrtf((float)((k + 1) * (k + 2)));
                    h.x -= co * zr; h.y -= co * zi;
                }
            } else {
                float r = dr[l * 4 + w], ph = dphi[l * 4 + w];
                float amp = r * cosf(ph), ang = r * sinf(ph);
                float ar = amp * cosf(ang), ai = amp * sinf(ang);
                if (k == i - 1) { float co = sqrtf((float)i); h.x += co * ar; h.y += co * ai; }
                if (i == k - 1) { float co = sqrtf((float)k); h.x -= co * ar; h.y += co * ai; }
            }
            H[tid] = h;
        }
        __syncthreads();
        float2* R2 = block_expm(H, P, E, T, red, &s_sh, 8, 3);
        if (tid < 64) {
            int i = tid >> 3;
            float ang;
            if (isSQ) {
                ang = ph2[l * 16 + w * 4 + w] * (float)i;          // intf2 pre-rot
            } else {
                ang = kp[l * 4 + w] * (float)(i * i);              // Kerr
                if (l < 3) ang += ph1[(l + 1) * 16 + w * 4 + w] * (float)i;
            }
            float si, co;
            sincosf(ang, &si, &co);
            float2 v = R2[tid];
            (isSQ ? g_sq : g_dp)[g * 64 + tid] =
                make_float2(v.x * co - v.y * si, v.x * si + v.y * co);
        }
    }
}

// ---------------------------------------------------------------------------
// Per-sample encoding: col 0 of expm(x(Ad - A)), layer-0 rot1 folded in.
// ---------------------------------------------------------------------------
__global__ void __launch_bounds__(64) precomp_enc(const float* __restrict__ x,
                                                  const float* __restrict__ ph1) {
    __shared__ float2 H[64], P[64], E[64], T[64];
    __shared__ float red[8];
    __shared__ int s_sh;
    const int bm = blockIdx.x, m = bm & 3, tid = threadIdx.x;
    const float xv = x[bm];
    if (tid < 64) {
        int i = tid >> 3, k = tid & 7;
        float h = 0.f;
        if (k == i - 1) h += xv * sqrtf((float)i);
        if (i == k - 1) h -= xv * sqrtf((float)k);
        H[tid] = make_float2(h, 0.f);
    }
    __syncthreads();
    float2* R = block_expm(H, P, E, T, red, &s_sh, 8, 3);
    if (tid < 8) {
        float ang = ph1[m * 4 + m] * (float)tid;
        float si, co;
        sincosf(ang, &si, &co);
        float2 v = R[tid * 8];
        g_enc[bm * 8 + tid] = make_float2(v.x * co - v.y * si, v.x * si + v.y * co);
    }
}

// ---------------------------------------------------------------------------
// Block-sparse BS apply, row-per-lane mapping (s-broadcast state loads).
// Thread = (row = tid&63, spectator-group sg = tid>>6, 16 spectators).
// Gate row cached in regs from TRANSPOSED layout (lane-stride 1, no conflict).
// Padded k slots read a DUMMY broadcast address (gate value there is 0, so
// 0 * finite = 0 — results bit-identical to the exact sparse contraction).
// Inner body = LDS.64 + 4 FFMA with compile-time spectator offsets.
// ---------------------------------------------------------------------------
template<int A1, int A2, int SPA, int SPB>
__device__ __forceinline__ void applyBS(const float2* __restrict__ gate,
                                        const float2* __restrict__ in,
                                        float2* __restrict__ out, int tid) {
    const int row = tid & 63;
    const int sg  = tid >> 6;
    const int a = row >> 3, b = row & 7, s = a + b;
    const int cmin = s > 7 ? s - 7 : 0;
    const int cnt  = (s > 7 ? 14 - s : s) + 1;
    float2 g[8];
#pragma unroll
    for (int k = 0; k < 8; k++) g[k] = gate[k * 64 + row];   // lane-stride 1: conflict-free
    const int sgo = sg * 2 * SPA;
    const int base = cmin * A1 + (s - cmin) * A2;
    int addr[8];
#pragma unroll
    for (int k = 0; k < 8; k++)
        addr[k] = (k < cnt ? base + k * (A1 - A2) : 0) + sgo;   // dummy=0: broadcast, gate=0
    const int ob = a * A1 + b * A2 + sgo;
#pragma unroll
    for (int i = 0; i < 16; i++) {
        const int off = (i >> 3) * SPA + (i & 7) * SPB;   // compile-time immediate
        float2 acc = make_float2(0.f, 0.f);
#pragma unroll
        for (int k = 0; k < 8; k++) {
            float2 sv = in[addr[k] + off];
            acc.x = fmaf(g[k].x, sv.x, fmaf(-g[k].y, sv.y, acc.x));
            acc.y = fmaf(g[k].x, sv.y, fmaf(g[k].y, sv.x, acc.y));
        }
        out[ob + off] = acc;
    }
}

// Single-mode 8x8 gate on mode with stride SW; spectator strides SL>SM>SS.
template<int SW, int SL, int SM, int SS>
__device__ __forceinline__ void applySingle(const float2* __restrict__ mg,
                                            float2* __restrict__ st, int tid) {
#pragma unroll
    for (int qq = 0; qq < 2; qq++) {
        int f = tid + qq * 256;
        int base = (f >> 6) * SL + ((f >> 3) & 7) * SM + (f & 7) * SS;
        float2 v[8];
#pragma unroll
        for (int k = 0; k < 8; k++) v[k] = st[base + k * SW];
#pragma unroll
        for (int i = 0; i < 8; i++) {
            float2 a = make_float2(0.f, 0.f);
#pragma unroll
            for (int k = 0; k < 8; k++) {
                float2 u = mg[i * 8 + k];
                a.x = fmaf(u.x, v[k].x, fmaf(-u.y, v[k].y, a.x));
                a.y = fmaf(u.x, v[k].y, fmaf(u.y, v[k].x, a.y));
            }
            st[base + i * SW] = a;   // inputs cached in v: in-place safe
        }
    }
}

__global__ void __launch_bounds__(256, 2) sim_kernel(float* __restrict__ out) {
    float2* sA = dynbuf;
    float2* sB = dynbuf + SZP;
    float2* gbuf = dynbuf + 2 * SZP;       // 512 float2
    __shared__ float2 enc[4][8];
    const int tid = threadIdx.x, b = blockIdx.x;

    if (tid < 32) enc[tid >> 3][tid & 7] = g_enc[b * 32 + tid];
    __syncthreads();
#pragma unroll
    for (int q = 0; q < 16; q++) {
        int idx = tid + q * 256;
        int i0 = idx >> 9, i1 = (idx >> 6) & 7, i2 = (idx >> 3) & 7, i3 = idx & 7;
        sA[i0 * 648 + i1 * 81 + i2 * 9 + i3] =
            cmul(cmul(enc[0][i0], enc[1][i1]), cmul(enc[2][i2], enc[3][i3]));
    }
    float2 *cur = sA, *nxt = sB;

    for (int l = 0; l < 4; l++) {
        for (int t = 0; t < 2; t++) {
            for (int p = 0; p < 6; p++) {
                __syncthreads();
                ((float4*)gbuf)[tid] = ((const float4*)(g_bs + (l * 12 + t * 6 + p) * 512))[tid];
                __syncthreads();
                switch (p) {
                    case 0: applyBS<648, 81,   9,  1>(gbuf, cur, nxt, tid); break;
                    case 1: applyBS<648,  9,  81,  1>(gbuf, cur, nxt, tid); break;
                    case 2: applyBS<648,  1,  81,  9>(gbuf, cur, nxt, tid); break;
                    case 3: applyBS< 81,  9, 648,  1>(gbuf, cur, nxt, tid); break;
                    case 4: applyBS< 81,  1, 648,  9>(gbuf, cur, nxt, tid); break;
                    case 5: applyBS<  9,  1, 648, 81>(gbuf, cur, nxt, tid); break;
                }
                { float2* tmp = cur; cur = nxt; nxt = tmp; }
            }
            const float2* gptr = (t == 0) ? g_sq : g_dp;
            for (int w = 0; w < 4; w++) {
                __syncthreads();
                if (tid < 64) gbuf[tid] = gptr[(l * 4 + w) * 64 + tid];
                __syncthreads();
                switch (w) {
                    case 0: applySingle<648,  81,  9, 1>(gbuf, cur, tid); break;
                    case 1: applySingle< 81, 648,  9, 1>(gbuf, cur, tid); break;
                    case 2: applySingle<  9, 648, 81, 1>(gbuf, cur, tid); break;
                    case 3: applySingle<  1, 648, 81, 9>(gbuf, cur, tid); break;
                }
            }
        }
    }
    __syncthreads();

    float acc[4] = {0.f, 0.f, 0.f, 0.f};
#pragma unroll
    for (int q = 0; q < 16; q++) {
        int idx = tid + q * 256;
        int i0 = idx >> 9, i1 = (idx >> 6) & 7, i2 = (idx >> 3) & 7, i3 = idx & 7;
        float2 v = cur[i0 * 648 + i1 * 81 + i2 * 9 + i3];
        float pr = v.x * v.x + v.y * v.y;
        acc[0] += (float)i0 * pr;
        acc[1] += (float)i1 * pr;
        acc[2] += (float)i2 * pr;
        acc[3] += (float)i3 * pr;
    }
    float* red = (float*)nxt;
#pragma unroll
    for (int w = 0; w < 4; w++) red[w * 256 + tid] = acc[w];
    __syncthreads();
    for (int s = 128; s > 0; s >>= 1) {
        if (tid < s) {
#pragma unroll
            for (int w = 0; w < 4; w++) red[w * 256 + tid] += red[w * 256 + tid + s];
        }
        __syncthreads();
    }
    if (tid < 4) out[b * 4 + tid] = red[tid * 256];
}

// ---------------------------------------------------------------------------
extern "C" void kernel_launch(void* const* d_in, const int* in_sizes, int n_in,
                              void* d_out, int out_size) {
    const float* x    = (const float*)d_in[0];
    const float* th1  = (const float*)d_in[1];
    const float* ph1  = (const float*)d_in[2];
    const float* th2  = (const float*)d_in[3];
    const float* ph2  = (const float*)d_in[4];
    const float* dr   = (const float*)d_in[5];
    const float* dphi = (const float*)d_in[6];
    const float* sr   = (const float*)d_in[7];
    const float* sphi = (const float*)d_in[8];
    const float* kp   = (const float*)d_in[9];
    float* out = (float*)d_out;

    const size_t smemG = 16384 * sizeof(float2) + 64 * sizeof(float);     // 131328
    const size_t smemS = (size_t)(2 * SZP + 512) * sizeof(float2);        //  87040
    cudaFuncSetAttribute(precomp_gates, cudaFuncAttributeMaxDynamicSharedMemorySize, (int)smemG);
    cudaFuncSetAttribute(sim_kernel,    cudaFuncAttributeMaxDynamicSharedMemorySize, (int)smemS);

    precomp_gates<<<80, 512, smemG>>>(th1, ph1, th2, ph2, dr, dphi, sr, sphi, kp);
    precomp_enc<<<16384, 64>>>(x, ph1);
    sim_kernel<<<4096, 256, smemS>>>(out);
}